// round 14
// baseline (speedup 1.0000x reference)
#include <cuda_runtime.h>
#include <cuda_fp16.h>
#include <math.h>
#include <stdint.h>

#define Bb  512
#define P1c 64
#define Lc  512
#define Hc  2048
#define Mc  (Bb * P1c)   // 32768 rows

// ---------------- scratch ----------------
__device__ float g_ysum[Bb];
__device__ float g_ysumsq[Bb];
__device__ __half g_yh[(size_t)Mc * Lc];               // filtered y fp16, 32 MB
__device__ __half g_a1[(size_t)Mc * Lc];               // LN1(x) fp16
__device__ __half g_a2[(size_t)Mc * Lc];               // LN2(y) fp16
__device__ __half g_ct[Lc * Lc];                       // C^T [N,K] fp16
__device__ __half g_w1t[(size_t)Hc * Lc];              // w1^T [2048,512] fp16
__device__ __half g_w2t[(size_t)Lc * Hc];              // w2^T [512,2048] fp16
__device__ __half g_z[(size_t)Mc * Hc];                // FFN hidden fp16, 128 MB

// ---------------- helpers ----------------
__device__ __forceinline__ uint32_t smem_u32(const void* p) {
    uint32_t a;
    asm("{ .reg .u64 t; cvta.to.shared.u64 t, %1; cvt.u32.u64 %0, t; }" : "=r"(a) : "l"(p));
    return a;
}
__device__ __forceinline__ void cp16(uint32_t dst, const void* src) {
    asm volatile("cp.async.cg.shared.global [%0], [%1], 16;"
                 :: "r"(dst), "l"((unsigned long long)__cvta_generic_to_global(src)));
}
__device__ __forceinline__ void cp16ca(uint32_t dst, const void* src) {
    asm volatile("cp.async.ca.shared.global [%0], [%1], 16;"
                 :: "r"(dst), "l"((unsigned long long)__cvta_generic_to_global(src)));
}
__device__ __forceinline__ void ldm4(uint32_t addr, uint32_t* r) {
    asm volatile("ldmatrix.sync.aligned.m8n8.x4.shared.b16 {%0,%1,%2,%3}, [%4];"
                 : "=r"(r[0]), "=r"(r[1]), "=r"(r[2]), "=r"(r[3]) : "r"(addr));
}
__device__ __forceinline__ void mma16816(float* c, const uint32_t* a,
                                         uint32_t b0, uint32_t b1) {
    asm volatile(
        "mma.sync.aligned.m16n8k16.row.col.f32.f16.f16.f32 "
        "{%0,%1,%2,%3}, {%4,%5,%6,%7}, {%8,%9}, {%0,%1,%2,%3};"
        : "+f"(c[0]), "+f"(c[1]), "+f"(c[2]), "+f"(c[3])
        : "r"(a[0]), "r"(a[1]), "r"(a[2]), "r"(a[3]), "r"(b0), "r"(b1));
}

// ---------------- fused LN1: stats over (P1,L) then LN -> fp16, one CTA/batch ----
__global__ void __launch_bounds__(256)
stats_ln_fp16(const float* __restrict__ x,
              const float* __restrict__ g, const float* __restrict__ bb,
              __half* __restrict__ out,
              float* __restrict__ ysum, float* __restrict__ ysumsq) {
    const int NPER = P1c * Lc;  // 32768
    const int b = blockIdx.x;
    const float4* xb = reinterpret_cast<const float4*>(x) + (size_t)b * (NPER / 4);
    float s = 0.f, ss = 0.f;
    for (int i = threadIdx.x; i < NPER / 4; i += blockDim.x) {
        float4 v = xb[i];
        s  += (v.x + v.y) + (v.z + v.w);
        ss += v.x * v.x + v.y * v.y + v.z * v.z + v.w * v.w;
    }
    __shared__ float sh_s[32], sh_ss[32];
    __shared__ float sh_m, sh_r;
    const int lane = threadIdx.x & 31, wid = threadIdx.x >> 5;
    for (int o = 16; o > 0; o >>= 1) {
        s  += __shfl_xor_sync(0xFFFFFFFFu, s,  o);
        ss += __shfl_xor_sync(0xFFFFFFFFu, ss, o);
    }
    if (lane == 0) { sh_s[wid] = s; sh_ss[wid] = ss; }
    __syncthreads();
    if (wid == 0) {
        const int nw = blockDim.x >> 5;
        s  = (lane < nw) ? sh_s[lane]  : 0.f;
        ss = (lane < nw) ? sh_ss[lane] : 0.f;
        for (int o = 16; o > 0; o >>= 1) {
            s  += __shfl_xor_sync(0xFFFFFFFFu, s,  o);
            ss += __shfl_xor_sync(0xFFFFFFFFu, ss, o);
        }
        if (lane == 0) {
            float m = s / NPER;
            float var = ss / NPER - m * m;
            sh_m = m;
            sh_r = rsqrtf(var + 1e-5f);
            ysum[b] = 0.f;
            ysumsq[b] = 0.f;
        }
    }
    __syncthreads();
    const float m = sh_m, r = sh_r;
    for (int i = threadIdx.x; i < NPER / 4; i += blockDim.x) {
        float4 v = xb[i];
        const int p  = i >> 7;
        const int c4 = (i & 127) << 2;
        float4 gv = *(const float4*)&g[p * Lc + c4];
        float4 bv = *(const float4*)&bb[p * Lc + c4];
        ushort4 h4;
        h4.x = __half_as_ushort(__float2half((v.x - m) * r * gv.x + bv.x));
        h4.y = __half_as_ushort(__float2half((v.y - m) * r * gv.y + bv.y));
        h4.z = __half_as_ushort(__float2half((v.z - m) * r * gv.z + bv.z));
        h4.w = __half_as_ushort(__float2half((v.w - m) * r * gv.w + bv.w));
        *(ushort4*)&out[(size_t)b * NPER + i * 4] = h4;
    }
}

// ---------------- LN2 (fp16 in) with inline stats finalize -> fp16 ----------------
__global__ void ln_fp16_h(const __half* __restrict__ x,
                          const float* __restrict__ ysum, const float* __restrict__ ysumsq,
                          const float* __restrict__ g, const float* __restrict__ bb,
                          __half* __restrict__ out) {
    size_t idx = (size_t)blockIdx.x * blockDim.x + threadIdx.x;
    int row = (int)(idx >> 7);
    int c4  = (int)(idx & 127) << 2;
    int b = row >> 6, p = row & 63;
    const float inv = 1.f / (P1c * Lc);
    float m = ysum[b] * inv;
    float r = rsqrtf(ysumsq[b] * inv - m * m + 1e-5f);
    ushort4 xv = *(const ushort4*)&x[(size_t)row * Lc + c4];
    float4 gv = *(const float4*)&g[p * Lc + c4];
    float4 bv = *(const float4*)&bb[p * Lc + c4];
    ushort4 h4;
    h4.x = __half_as_ushort(__float2half((__half2float(__ushort_as_half(xv.x)) - m) * r * gv.x + bv.x));
    h4.y = __half_as_ushort(__float2half((__half2float(__ushort_as_half(xv.y)) - m) * r * gv.y + bv.y));
    h4.z = __half_as_ushort(__float2half((__half2float(__ushort_as_half(xv.z)) - m) * r * gv.z + bv.z));
    h4.w = __half_as_ushort(__float2half((__half2float(__ushort_as_half(xv.w)) - m) * r * gv.w + bv.w));
    *(ushort4*)&out[(size_t)row * Lc + c4] = h4;
}

// ---------------- Ct[n][k] = w[(n-k)&511]/sqrt(L), fp16 ----------------
__global__ void build_ct(const float* __restrict__ w, __half* __restrict__ ct) {
    int k = blockIdx.x * blockDim.x + threadIdx.x;
    int n = blockIdx.y;
    ct[n * Lc + k] = __float2half(w[(n - k) & (Lc - 1)] * 0.04419417382415922f);
}

// ---------------- transpose -> fp16: [K,N] fp32 -> [N,K] ----------------
__global__ void transpose_h(const float* __restrict__ in, __half* __restrict__ outp,
                            int K, int N) {
    __shared__ float t[32][33];
    int n0 = blockIdx.x * 32, k0 = blockIdx.y * 32;
    int tx = threadIdx.x, ty = threadIdx.y;
    for (int i = ty; i < 32; i += 8)
        t[i][tx] = in[(size_t)(k0 + i) * N + n0 + tx];
    __syncthreads();
    for (int i = ty; i < 32; i += 8)
        outp[(size_t)(n0 + i) * K + k0 + tx] = __float2half(t[tx][i]);
}

// ---------------- HMMA fp16 GEMM (R11 best config, reverted) ----------------
// CTA tile 128x128, BK=64, 4 warps (2M x 2N), warp tile 64x64.
// 2-stage cp.async pipeline, 3 CTAs/SM, B-frag halves (reg cap 170),
// B loaded with .ca. One sync per 64-deep k-tile. kt loop unrolled x2.
// EPI 0: Dout=acc
// EPI 1: Z = fp16(relu(acc+bias))
// EPI 2: Dout=acc+bias+res
// EPI 3: Z = fp16(acc), plus per-batch sum/sumsq atomics (ysum/ysumsq)
#define RSTRIDE 144                     // 128B data + 16B pad per k64-row
#define MTILE_B (128 * RSTRIDE)         // 18432 per matrix
#define STG     (2 * MTILE_B)           // A, B = 36864
#define DSMEM   (2 * STG)               // 73728

template <int EPI, int K, int N>
__global__ void __launch_bounds__(128, 3)
hmma_gemm(const __half* __restrict__ A, const __half* __restrict__ B,
          float* __restrict__ Dout, __half* __restrict__ Z,
          const float* __restrict__ bias, const float* __restrict__ res,
          float* __restrict__ ysum, float* __restrict__ ysumsq) {
    extern __shared__ char smem[];
    const uint32_t sb = smem_u32(smem);
    const int tid = threadIdx.x, wid = tid >> 5, lane = tid & 31;
    const int wy = wid & 1, wx = wid >> 1;            // 2 M-warps x 2 N-warps
    const int m0 = blockIdx.y * 128, n0 = blockIdx.x * 128;

    const uint32_t offA = (uint32_t)((wy * 64 + (lane & 7) + ((lane >> 3) & 1) * 8) * RSTRIDE
                                     + (lane >> 4) * 16);
    const uint32_t offB = (uint32_t)((wx * 64 + (lane & 7) + (lane >> 4) * 8) * RSTRIDE
                                     + ((lane >> 3) & 1) * 16);

    auto load_stage = [&](int s, int kt) {
        const uint32_t ab = sb + s * STG;
#pragma unroll
        for (int i = 0; i < 8; i++) {
            const int j = tid + (i << 7);       // 0..1023
            const int row = j >> 3, c = j & 7;
            const uint32_t off = row * RSTRIDE + c * 16;
            cp16(ab + off, A + (size_t)(m0 + row) * K + (size_t)kt * 64 + c * 8);
            cp16ca(ab + MTILE_B + off,
                   B + (size_t)(n0 + row) * K + (size_t)kt * 64 + c * 8);
        }
        asm volatile("cp.async.commit_group;");
    };

    float acc[4][8][4];
#pragma unroll
    for (int mi = 0; mi < 4; mi++)
#pragma unroll
        for (int ni = 0; ni < 8; ni++)
#pragma unroll
            for (int q = 0; q < 4; q++) acc[mi][ni][q] = 0.f;

    constexpr int nkt = K >> 6;       // 8 / 8 / 32 (all even)
    load_stage(0, 0);

#pragma unroll 2
    for (int kt = 0; kt < nkt; kt++) {
        asm volatile("cp.async.wait_group 0;" ::: "memory");
        __syncthreads();
        if (kt + 1 < nkt) load_stage((kt + 1) & 1, kt + 1);

        const uint32_t st = sb + (kt & 1) * STG;
#pragma unroll
        for (int kk = 0; kk < 4; kk++) {
            uint32_t ah[4][4];
#pragma unroll
            for (int mi = 0; mi < 4; mi++)
                ldm4(st + offA + mi * (16 * RSTRIDE) + kk * 32, ah[mi]);
#pragma unroll
            for (int half = 0; half < 2; half++) {
                uint32_t bf[2][4];
#pragma unroll
                for (int n2 = 0; n2 < 2; n2++)
                    ldm4(st + MTILE_B + offB + (half * 2 + n2) * (16 * RSTRIDE) + kk * 32,
                         bf[n2]);
#pragma unroll
                for (int mi = 0; mi < 4; mi++)
#pragma unroll
                    for (int n2 = 0; n2 < 2; n2++) {
                        const int nf = half * 2 + n2;
                        mma16816(acc[mi][nf * 2 + 0], ah[mi], bf[n2][0], bf[n2][1]);
                        mma16816(acc[mi][nf * 2 + 1], ah[mi], bf[n2][2], bf[n2][3]);
                    }
            }
        }
    }

    // ---- epilogue ----
    const int r0 = m0 + wy * 64 + (lane >> 2);
    const int cbase = n0 + wx * 64 + (lane & 3) * 2;
    float s = 0.f, ss = 0.f;
#pragma unroll
    for (int mi = 0; mi < 4; mi++) {
#pragma unroll
        for (int ni = 0; ni < 8; ni++) {
            const int col = cbase + ni * 8;
            const int ra = r0 + mi * 16;
            const int rb = ra + 8;
            float* c = acc[mi][ni];
            if (EPI == 0) {
                *(float2*)&Dout[(size_t)ra * N + col] = make_float2(c[0], c[1]);
                *(float2*)&Dout[(size_t)rb * N + col] = make_float2(c[2], c[3]);
            } else if (EPI == 1) {
                const float2 bq = *(const float2*)&bias[col];
                ushort2 h0, h1;
                h0.x = __half_as_ushort(__float2half(fmaxf(c[0] + bq.x, 0.f)));
                h0.y = __half_as_ushort(__float2half(fmaxf(c[1] + bq.y, 0.f)));
                h1.x = __half_as_ushort(__float2half(fmaxf(c[2] + bq.x, 0.f)));
                h1.y = __half_as_ushort(__float2half(fmaxf(c[3] + bq.y, 0.f)));
                *(ushort2*)&Z[(size_t)ra * N + col] = h0;
                *(ushort2*)&Z[(size_t)rb * N + col] = h1;
            } else if (EPI == 2) {
                const float2 bq = *(const float2*)&bias[col];
                const float2 q0 = *(const float2*)&res[(size_t)ra * N + col];
                const float2 q1 = *(const float2*)&res[(size_t)rb * N + col];
                *(float2*)&Dout[(size_t)ra * N + col] =
                    make_float2(c[0] + bq.x + q0.x, c[1] + bq.y + q0.y);
                *(float2*)&Dout[(size_t)rb * N + col] =
                    make_float2(c[2] + bq.x + q1.x, c[3] + bq.y + q1.y);
            } else {
                ushort2 h0, h1;
                h0.x = __half_as_ushort(__float2half(c[0]));
                h0.y = __half_as_ushort(__float2half(c[1]));
                h1.x = __half_as_ushort(__float2half(c[2]));
                h1.y = __half_as_ushort(__float2half(c[3]));
                *(ushort2*)&Z[(size_t)ra * N + col] = h0;
                *(ushort2*)&Z[(size_t)rb * N + col] = h1;
                s  += (c[0] + c[1]) + (c[2] + c[3]);
                ss += c[0] * c[0] + c[1] * c[1] + c[2] * c[2] + c[3] * c[3];
            }
        }
    }
    if (EPI == 3) {
        // warp rows m0 + wy*64 .. +63 lie in exactly one 64-row batch
#pragma unroll
        for (int o = 16; o > 0; o >>= 1) {
            s  += __shfl_xor_sync(0xFFFFFFFFu, s,  o);
            ss += __shfl_xor_sync(0xFFFFFFFFu, ss, o);
        }
        if (lane == 0) {
            const int b = (m0 >> 6) + wy;
            atomicAdd(&ysum[b],   s);
            atomicAdd(&ysumsq[b], ss);
        }
    }
}

// ---------------- launcher ----------------
extern "C" void kernel_launch(void* const* d_in, const int* in_sizes, int n_in,
                              void* d_out, int out_size) {
    const float* x    = (const float*)d_in[0];
    const float* w    = (const float*)d_in[1];
    const float* ln1w = (const float*)d_in[2];
    const float* ln1b = (const float*)d_in[3];
    const float* ln2w = (const float*)d_in[4];
    const float* ln2b = (const float*)d_in[5];
    const float* w1   = (const float*)d_in[6];
    const float* b1   = (const float*)d_in[7];
    const float* w2   = (const float*)d_in[8];
    const float* b2   = (const float*)d_in[9];
    float* out = (float*)d_out;

    float *ysum, *ysumsq;
    __half *yh, *a1, *a2, *ct, *w1t, *w2t, *z;
    cudaGetSymbolAddress((void**)&ysum,   g_ysum);
    cudaGetSymbolAddress((void**)&ysumsq, g_ysumsq);
    cudaGetSymbolAddress((void**)&yh,     g_yh);
    cudaGetSymbolAddress((void**)&a1,     g_a1);
    cudaGetSymbolAddress((void**)&a2,     g_a2);
    cudaGetSymbolAddress((void**)&ct,     g_ct);
    cudaGetSymbolAddress((void**)&w1t,    g_w1t);
    cudaGetSymbolAddress((void**)&w2t,    g_w2t);
    cudaGetSymbolAddress((void**)&z,      g_z);

    cudaFuncSetAttribute(hmma_gemm<3, Lc, Lc>, cudaFuncAttributeMaxDynamicSharedMemorySize, DSMEM);
    cudaFuncSetAttribute(hmma_gemm<1, Lc, Hc>, cudaFuncAttributeMaxDynamicSharedMemorySize, DSMEM);
    cudaFuncSetAttribute(hmma_gemm<2, Hc, Lc>, cudaFuncAttributeMaxDynamicSharedMemorySize, DSMEM);

    // 1) fused LN1 stats + LN + fp16 (also zeroes y accumulators)
    stats_ln_fp16<<<Bb, 256>>>(x, ln1w, ln1b, a1, ysum, ysumsq);
    // 2) operand prep (fp16)
    build_ct<<<dim3(2, Lc), 256>>>(w, ct);
    transpose_h<<<dim3(Hc / 32, Lc / 32), dim3(32, 8)>>>(w1, w1t, Lc, Hc);
    transpose_h<<<dim3(Lc / 32, Hc / 32), dim3(32, 8)>>>(w2, w2t, Hc, Lc);
    // 3) y = LN1(x) @ C  (fp16 out + fused stats)   M=32768 K=512 N=512
    hmma_gemm<3, Lc, Lc><<<dim3(Lc / 128, Mc / 128), 128, DSMEM>>>(
        a1, ct, nullptr, yh, nullptr, nullptr, ysum, ysumsq);
    // 4) LN2 -> fp16 (stats finalized inline from ysum/ysumsq)
    ln_fp16_h<<<(Mc * Lc / 4) / 256, 256>>>(yh, ysum, ysumsq, ln2w, ln2b, a2);
    // 5) z = fp16(relu(LN2(y) @ w1 + b1))   M=32768 K=512 N=2048
    hmma_gemm<1, Lc, Hc><<<dim3(Hc / 128, Mc / 128), 128, DSMEM>>>(
        a2, w1t, nullptr, z, b1, nullptr, nullptr, nullptr);
    // 6) out = z @ w2 + b2 + x              M=32768 K=2048 N=512
    hmma_gemm<2, Hc, Lc><<<dim3(Lc / 128, Mc / 128), 128, DSMEM>>>(
        z, w2t, out, nullptr, b2, x, nullptr, nullptr);
}

// round 15
// speedup vs baseline: 1.1435x; 1.1435x over previous
#include <cuda_runtime.h>
#include <cuda_fp16.h>
#include <math.h>
#include <stdint.h>

#define Bb  512
#define P1c 64
#define Lc  512
#define Hc  2048
#define Mc  (Bb * P1c)   // 32768 rows

// ---------------- scratch ----------------
__device__ float g_mu1[Bb];
__device__ float g_rstd1[Bb];
__device__ float g_mu2[Bb];
__device__ float g_rstd2[Bb];
__device__ float g_ysum[Bb];
__device__ float g_ysumsq[Bb];
__device__ __half g_yh[(size_t)Mc * Lc];               // filtered y fp16, 32 MB
__device__ __half g_a1[(size_t)Mc * Lc];               // LN1(x) fp16
__device__ __half g_a2[(size_t)Mc * Lc];               // LN2(y) fp16
__device__ __half g_ct[Lc * Lc];                       // C^T [N,K] fp16
__device__ __half g_w1t[(size_t)Hc * Lc];              // w1^T [2048,512] fp16
__device__ __half g_w2t[(size_t)Lc * Hc];              // w2^T [512,2048] fp16
__device__ __half g_z[(size_t)Mc * Hc];                // FFN hidden fp16, 128 MB

// ---------------- helpers ----------------
__device__ __forceinline__ uint32_t smem_u32(const void* p) {
    uint32_t a;
    asm("{ .reg .u64 t; cvta.to.shared.u64 t, %1; cvt.u32.u64 %0, t; }" : "=r"(a) : "l"(p));
    return a;
}
__device__ __forceinline__ void cp16(uint32_t dst, const void* src) {
    asm volatile("cp.async.cg.shared.global [%0], [%1], 16;"
                 :: "r"(dst), "l"((unsigned long long)__cvta_generic_to_global(src)));
}
__device__ __forceinline__ void cp16ca(uint32_t dst, const void* src) {
    asm volatile("cp.async.ca.shared.global [%0], [%1], 16;"
                 :: "r"(dst), "l"((unsigned long long)__cvta_generic_to_global(src)));
}
__device__ __forceinline__ void ldm4(uint32_t addr, uint32_t* r) {
    asm volatile("ldmatrix.sync.aligned.m8n8.x4.shared.b16 {%0,%1,%2,%3}, [%4];"
                 : "=r"(r[0]), "=r"(r[1]), "=r"(r[2]), "=r"(r[3]) : "r"(addr));
}
__device__ __forceinline__ void mma16816(float* c, const uint32_t* a,
                                         uint32_t b0, uint32_t b1) {
    asm volatile(
        "mma.sync.aligned.m16n8k16.row.col.f32.f16.f16.f32 "
        "{%0,%1,%2,%3}, {%4,%5,%6,%7}, {%8,%9}, {%0,%1,%2,%3};"
        : "+f"(c[0]), "+f"(c[1]), "+f"(c[2]), "+f"(c[3])
        : "r"(a[0]), "r"(a[1]), "r"(a[2]), "r"(a[3]), "r"(b0), "r"(b1));
}

// ---------------- per-batch mean / rstd over (P1, L) fp32 input ----------------
// Also zeroes the per-batch y accumulators (replaces the old zero_acc launch).
__global__ void batch_stats(const float* __restrict__ x,
                            float* __restrict__ mu, float* __restrict__ rstd,
                            float* __restrict__ ysum, float* __restrict__ ysumsq) {
    const int NPER = P1c * Lc;
    const int b = blockIdx.x;
    const float4* xb = reinterpret_cast<const float4*>(x) + (size_t)b * (NPER / 4);
    float s = 0.f, ss = 0.f;
    for (int i = threadIdx.x; i < NPER / 4; i += blockDim.x) {
        float4 v = xb[i];
        s  += (v.x + v.y) + (v.z + v.w);
        ss += v.x * v.x + v.y * v.y + v.z * v.z + v.w * v.w;
    }
    __shared__ float sh_s[32], sh_ss[32];
    const int lane = threadIdx.x & 31, wid = threadIdx.x >> 5;
    for (int o = 16; o > 0; o >>= 1) {
        s  += __shfl_xor_sync(0xFFFFFFFFu, s,  o);
        ss += __shfl_xor_sync(0xFFFFFFFFu, ss, o);
    }
    if (lane == 0) { sh_s[wid] = s; sh_ss[wid] = ss; }
    __syncthreads();
    if (wid == 0) {
        const int nw = blockDim.x >> 5;
        s  = (lane < nw) ? sh_s[lane]  : 0.f;
        ss = (lane < nw) ? sh_ss[lane] : 0.f;
        for (int o = 16; o > 0; o >>= 1) {
            s  += __shfl_xor_sync(0xFFFFFFFFu, s,  o);
            ss += __shfl_xor_sync(0xFFFFFFFFu, ss, o);
        }
        if (lane == 0) {
            float m = s / NPER;
            float var = ss / NPER - m * m;
            mu[b] = m;
            rstd[b] = rsqrtf(var + 1e-5f);
            ysum[b] = 0.f;
            ysumsq[b] = 0.f;
        }
    }
}

// ---------------- finalize y stats ----------------
__global__ void finalize_stats(const float* __restrict__ s, const float* __restrict__ ss,
                               float* __restrict__ mu, float* __restrict__ rstd) {
    int i = threadIdx.x + blockIdx.x * blockDim.x;
    if (i < Bb) {
        const float inv = 1.f / (P1c * Lc);
        float m = s[i] * inv;
        float var = ss[i] * inv - m * m;
        mu[i] = m;
        rstd[i] = rsqrtf(var + 1e-5f);
    }
}

// ---------------- LN(fp32 in) -> fp16 ----------------
__global__ void ln_fp16(const float* __restrict__ x,
                        const float* __restrict__ mu, const float* __restrict__ rstd,
                        const float* __restrict__ g, const float* __restrict__ bb,
                        __half* __restrict__ out) {
    size_t idx = (size_t)blockIdx.x * blockDim.x + threadIdx.x;
    int row = (int)(idx >> 7);
    int c4  = (int)(idx & 127) << 2;
    int b = row >> 6, p = row & 63;
    float m = mu[b], r = rstd[b];
    float4 v  = *(const float4*)&x[(size_t)row * Lc + c4];
    float4 gv = *(const float4*)&g[p * Lc + c4];
    float4 bv = *(const float4*)&bb[p * Lc + c4];
    ushort4 h4;
    h4.x = __half_as_ushort(__float2half((v.x - m) * r * gv.x + bv.x));
    h4.y = __half_as_ushort(__float2half((v.y - m) * r * gv.y + bv.y));
    h4.z = __half_as_ushort(__float2half((v.z - m) * r * gv.z + bv.z));
    h4.w = __half_as_ushort(__float2half((v.w - m) * r * gv.w + bv.w));
    *(ushort4*)&out[(size_t)row * Lc + c4] = h4;
}

// ---------------- LN(fp16 in) -> fp16 ----------------
__global__ void ln_fp16_h(const __half* __restrict__ x,
                          const float* __restrict__ mu, const float* __restrict__ rstd,
                          const float* __restrict__ g, const float* __restrict__ bb,
                          __half* __restrict__ out) {
    size_t idx = (size_t)blockIdx.x * blockDim.x + threadIdx.x;
    int row = (int)(idx >> 7);
    int c4  = (int)(idx & 127) << 2;
    int b = row >> 6, p = row & 63;
    float m = mu[b], r = rstd[b];
    ushort4 xv = *(const ushort4*)&x[(size_t)row * Lc + c4];
    float4 gv = *(const float4*)&g[p * Lc + c4];
    float4 bv = *(const float4*)&bb[p * Lc + c4];
    ushort4 h4;
    h4.x = __half_as_ushort(__float2half((__half2float(__ushort_as_half(xv.x)) - m) * r * gv.x + bv.x));
    h4.y = __half_as_ushort(__float2half((__half2float(__ushort_as_half(xv.y)) - m) * r * gv.y + bv.y));
    h4.z = __half_as_ushort(__float2half((__half2float(__ushort_as_half(xv.z)) - m) * r * gv.z + bv.z));
    h4.w = __half_as_ushort(__float2half((__half2float(__ushort_as_half(xv.w)) - m) * r * gv.w + bv.w));
    *(ushort4*)&out[(size_t)row * Lc + c4] = h4;
}

// ---------------- Ct[n][k] = w[(n-k)&511]/sqrt(L), fp16 ----------------
__global__ void build_ct(const float* __restrict__ w, __half* __restrict__ ct) {
    int k = blockIdx.x * blockDim.x + threadIdx.x;
    int n = blockIdx.y;
    ct[n * Lc + k] = __float2half(w[(n - k) & (Lc - 1)] * 0.04419417382415922f);
}

// ---------------- transpose -> fp16: [K,N] fp32 -> [N,K] ----------------
__global__ void transpose_h(const float* __restrict__ in, __half* __restrict__ outp,
                            int K, int N) {
    __shared__ float t[32][33];
    int n0 = blockIdx.x * 32, k0 = blockIdx.y * 32;
    int tx = threadIdx.x, ty = threadIdx.y;
    for (int i = ty; i < 32; i += 8)
        t[i][tx] = in[(size_t)(k0 + i) * N + n0 + tx];
    __syncthreads();
    for (int i = ty; i < 32; i += 8)
        outp[(size_t)(n0 + i) * K + k0 + tx] = __float2half(t[tx][i]);
}

// ---------------- HMMA fp16 GEMM (exact R11 best config) ----------------
// CTA tile 128x128, BK=64, 4 warps (2M x 2N), warp tile 64x64.
// 2-stage cp.async pipeline, 3 CTAs/SM, B-frag halves (reg cap 170),
// B loaded with .ca. One sync per 64-deep k-tile. NO kt-loop unroll pragma.
// EPI 0: Dout=acc
// EPI 1: Z = fp16(relu(acc+bias))
// EPI 2: Dout=acc+bias+res
// EPI 3: Z = fp16(acc), plus per-batch sum/sumsq atomics (ysum/ysumsq)
#define RSTRIDE 144                     // 128B data + 16B pad per k64-row
#define MTILE_B (128 * RSTRIDE)         // 18432 per matrix
#define STG     (2 * MTILE_B)           // A, B = 36864
#define DSMEM   (2 * STG)               // 73728

template <int EPI, int K, int N>
__global__ void __launch_bounds__(128, 3)
hmma_gemm(const __half* __restrict__ A, const __half* __restrict__ B,
          float* __restrict__ Dout, __half* __restrict__ Z,
          const float* __restrict__ bias, const float* __restrict__ res,
          float* __restrict__ ysum, float* __restrict__ ysumsq) {
    extern __shared__ char smem[];
    const uint32_t sb = smem_u32(smem);
    const int tid = threadIdx.x, wid = tid >> 5, lane = tid & 31;
    const int wy = wid & 1, wx = wid >> 1;            // 2 M-warps x 2 N-warps
    const int m0 = blockIdx.y * 128, n0 = blockIdx.x * 128;

    const uint32_t offA = (uint32_t)((wy * 64 + (lane & 7) + ((lane >> 3) & 1) * 8) * RSTRIDE
                                     + (lane >> 4) * 16);
    const uint32_t offB = (uint32_t)((wx * 64 + (lane & 7) + (lane >> 4) * 8) * RSTRIDE
                                     + ((lane >> 3) & 1) * 16);

    auto load_stage = [&](int s, int kt) {
        const uint32_t ab = sb + s * STG;
#pragma unroll
        for (int i = 0; i < 8; i++) {
            const int j = tid + (i << 7);       // 0..1023
            const int row = j >> 3, c = j & 7;
            const uint32_t off = row * RSTRIDE + c * 16;
            cp16(ab + off, A + (size_t)(m0 + row) * K + (size_t)kt * 64 + c * 8);
            cp16ca(ab + MTILE_B + off,
                   B + (size_t)(n0 + row) * K + (size_t)kt * 64 + c * 8);
        }
        asm volatile("cp.async.commit_group;");
    };

    float acc[4][8][4];
#pragma unroll
    for (int mi = 0; mi < 4; mi++)
#pragma unroll
        for (int ni = 0; ni < 8; ni++)
#pragma unroll
            for (int q = 0; q < 4; q++) acc[mi][ni][q] = 0.f;

    constexpr int nkt = K >> 6;       // 8 / 8 / 32
    load_stage(0, 0);

    for (int kt = 0; kt < nkt; kt++) {
        asm volatile("cp.async.wait_group 0;" ::: "memory");
        __syncthreads();
        if (kt + 1 < nkt) load_stage((kt + 1) & 1, kt + 1);

        const uint32_t st = sb + (kt & 1) * STG;
#pragma unroll
        for (int kk = 0; kk < 4; kk++) {
            uint32_t ah[4][4];
#pragma unroll
            for (int mi = 0; mi < 4; mi++)
                ldm4(st + offA + mi * (16 * RSTRIDE) + kk * 32, ah[mi]);
#pragma unroll
            for (int half = 0; half < 2; half++) {
                uint32_t bf[2][4];
#pragma unroll
                for (int n2 = 0; n2 < 2; n2++)
                    ldm4(st + MTILE_B + offB + (half * 2 + n2) * (16 * RSTRIDE) + kk * 32,
                         bf[n2]);
#pragma unroll
                for (int mi = 0; mi < 4; mi++)
#pragma unroll
                    for (int n2 = 0; n2 < 2; n2++) {
                        const int nf = half * 2 + n2;
                        mma16816(acc[mi][nf * 2 + 0], ah[mi], bf[n2][0], bf[n2][1]);
                        mma16816(acc[mi][nf * 2 + 1], ah[mi], bf[n2][2], bf[n2][3]);
                    }
            }
        }
    }

    // ---- epilogue ----
    const int r0 = m0 + wy * 64 + (lane >> 2);
    const int cbase = n0 + wx * 64 + (lane & 3) * 2;
    float s = 0.f, ss = 0.f;
#pragma unroll
    for (int mi = 0; mi < 4; mi++) {
#pragma unroll
        for (int ni = 0; ni < 8; ni++) {
            const int col = cbase + ni * 8;
            const int ra = r0 + mi * 16;
            const int rb = ra + 8;
            float* c = acc[mi][ni];
            if (EPI == 0) {
                *(float2*)&Dout[(size_t)ra * N + col] = make_float2(c[0], c[1]);
                *(float2*)&Dout[(size_t)rb * N + col] = make_float2(c[2], c[3]);
            } else if (EPI == 1) {
                const float2 bq = *(const float2*)&bias[col];
                ushort2 h0, h1;
                h0.x = __half_as_ushort(__float2half(fmaxf(c[0] + bq.x, 0.f)));
                h0.y = __half_as_ushort(__float2half(fmaxf(c[1] + bq.y, 0.f)));
                h1.x = __half_as_ushort(__float2half(fmaxf(c[2] + bq.x, 0.f)));
                h1.y = __half_as_ushort(__float2half(fmaxf(c[3] + bq.y, 0.f)));
                *(ushort2*)&Z[(size_t)ra * N + col] = h0;
                *(ushort2*)&Z[(size_t)rb * N + col] = h1;
            } else if (EPI == 2) {
                const float2 bq = *(const float2*)&bias[col];
                const float2 q0 = *(const float2*)&res[(size_t)ra * N + col];
                const float2 q1 = *(const float2*)&res[(size_t)rb * N + col];
                *(float2*)&Dout[(size_t)ra * N + col] =
                    make_float2(c[0] + bq.x + q0.x, c[1] + bq.y + q0.y);
                *(float2*)&Dout[(size_t)rb * N + col] =
                    make_float2(c[2] + bq.x + q1.x, c[3] + bq.y + q1.y);
            } else {
                ushort2 h0, h1;
                h0.x = __half_as_ushort(__float2half(c[0]));
                h0.y = __half_as_ushort(__float2half(c[1]));
                h1.x = __half_as_ushort(__float2half(c[2]));
                h1.y = __half_as_ushort(__float2half(c[3]));
                *(ushort2*)&Z[(size_t)ra * N + col] = h0;
                *(ushort2*)&Z[(size_t)rb * N + col] = h1;
                s  += (c[0] + c[1]) + (c[2] + c[3]);
                ss += c[0] * c[0] + c[1] * c[1] + c[2] * c[2] + c[3] * c[3];
            }
        }
    }
    if (EPI == 3) {
        // warp rows m0 + wy*64 .. +63 lie in exactly one 64-row batch
#pragma unroll
        for (int o = 16; o > 0; o >>= 1) {
            s  += __shfl_xor_sync(0xFFFFFFFFu, s,  o);
            ss += __shfl_xor_sync(0xFFFFFFFFu, ss, o);
        }
        if (lane == 0) {
            const int b = (m0 >> 6) + wy;
            atomicAdd(&ysum[b],   s);
            atomicAdd(&ysumsq[b], ss);
        }
    }
}

// ---------------- launcher ----------------
extern "C" void kernel_launch(void* const* d_in, const int* in_sizes, int n_in,
                              void* d_out, int out_size) {
    const float* x    = (const float*)d_in[0];
    const float* w    = (const float*)d_in[1];
    const float* ln1w = (const float*)d_in[2];
    const float* ln1b = (const float*)d_in[3];
    const float* ln2w = (const float*)d_in[4];
    const float* ln2b = (const float*)d_in[5];
    const float* w1   = (const float*)d_in[6];
    const float* b1   = (const float*)d_in[7];
    const float* w2   = (const float*)d_in[8];
    const float* b2   = (const float*)d_in[9];
    float* out = (float*)d_out;

    float *mu1, *rstd1, *mu2, *rstd2, *ysum, *ysumsq;
    __half *yh, *a1, *a2, *ct, *w1t, *w2t, *z;
    cudaGetSymbolAddress((void**)&mu1,    g_mu1);
    cudaGetSymbolAddress((void**)&rstd1,  g_rstd1);
    cudaGetSymbolAddress((void**)&mu2,    g_mu2);
    cudaGetSymbolAddress((void**)&rstd2,  g_rstd2);
    cudaGetSymbolAddress((void**)&ysum,   g_ysum);
    cudaGetSymbolAddress((void**)&ysumsq, g_ysumsq);
    cudaGetSymbolAddress((void**)&yh,     g_yh);
    cudaGetSymbolAddress((void**)&a1,     g_a1);
    cudaGetSymbolAddress((void**)&a2,     g_a2);
    cudaGetSymbolAddress((void**)&ct,     g_ct);
    cudaGetSymbolAddress((void**)&w1t,    g_w1t);
    cudaGetSymbolAddress((void**)&w2t,    g_w2t);
    cudaGetSymbolAddress((void**)&z,      g_z);

    cudaFuncSetAttribute(hmma_gemm<3, Lc, Lc>, cudaFuncAttributeMaxDynamicSharedMemorySize, DSMEM);
    cudaFuncSetAttribute(hmma_gemm<1, Lc, Hc>, cudaFuncAttributeMaxDynamicSharedMemorySize, DSMEM);
    cudaFuncSetAttribute(hmma_gemm<2, Hc, Lc>, cudaFuncAttributeMaxDynamicSharedMemorySize, DSMEM);

    // 1) LN1 stats (also zeroes y accumulators) + LN1 -> fp16
    batch_stats<<<Bb, 256>>>(x, mu1, rstd1, ysum, ysumsq);
    ln_fp16<<<(Mc * Lc / 4) / 256, 256>>>(x, mu1, rstd1, ln1w, ln1b, a1);
    // 2) operand prep (fp16)
    build_ct<<<dim3(2, Lc), 256>>>(w, ct);
    transpose_h<<<dim3(Hc / 32, Lc / 32), dim3(32, 8)>>>(w1, w1t, Lc, Hc);
    transpose_h<<<dim3(Lc / 32, Hc / 32), dim3(32, 8)>>>(w2, w2t, Hc, Lc);
    // 3) y = LN1(x) @ C  (fp16 out + fused stats)   M=32768 K=512 N=512
    hmma_gemm<3, Lc, Lc><<<dim3(Lc / 128, Mc / 128), 128, DSMEM>>>(
        a1, ct, nullptr, yh, nullptr, nullptr, ysum, ysumsq);
    // 4) finalize stats + LN2 -> fp16
    finalize_stats<<<2, 256>>>(ysum, ysumsq, mu2, rstd2);
    ln_fp16_h<<<(Mc * Lc / 4) / 256, 256>>>(yh, mu2, rstd2, ln2w, ln2b, a2);
    // 5) z = fp16(relu(LN2(y) @ w1 + b1))   M=32768 K=512 N=2048
    hmma_gemm<1, Lc, Hc><<<dim3(Hc / 128, Mc / 128), 128, DSMEM>>>(
        a2, w1t, nullptr, z, b1, nullptr, nullptr, nullptr);
    // 6) out = z @ w2 + b2 + x              M=32768 K=2048 N=512
    hmma_gemm<2, Hc, Lc><<<dim3(Lc / 128, Mc / 128), 128, DSMEM>>>(
        z, w2t, out, nullptr, b2, x, nullptr, nullptr);
}

// round 16
// speedup vs baseline: 1.1525x; 1.0079x over previous
#include <cuda_runtime.h>
#include <cuda_fp16.h>
#include <math.h>
#include <stdint.h>

#define Bb  512
#define P1c 64
#define Lc  512
#define Hc  2048
#define Mc  (Bb * P1c)   // 32768 rows

// ---------------- scratch ----------------
__device__ float g_mu1[Bb];
__device__ float g_rstd1[Bb];
__device__ float g_ysum[Bb];
__device__ float g_ysumsq[Bb];
__device__ __half g_yh[(size_t)Mc * Lc];               // filtered y fp16, 32 MB
__device__ __half g_a1[(size_t)Mc * Lc];               // LN1(x) fp16
__device__ __half g_a2[(size_t)Mc * Lc];               // LN2(y) fp16
__device__ __half g_ct[Lc * Lc];                       // C^T [N,K] fp16
__device__ __half g_w1t[(size_t)Hc * Lc];              // w1^T [2048,512] fp16
__device__ __half g_w2t[(size_t)Lc * Hc];              // w2^T [512,2048] fp16
__device__ __half g_z[(size_t)Mc * Hc];                // FFN hidden fp16, 128 MB

// ---------------- helpers ----------------
__device__ __forceinline__ uint32_t smem_u32(const void* p) {
    uint32_t a;
    asm("{ .reg .u64 t; cvta.to.shared.u64 t, %1; cvt.u32.u64 %0, t; }" : "=r"(a) : "l"(p));
    return a;
}
__device__ __forceinline__ void cp16(uint32_t dst, const void* src) {
    asm volatile("cp.async.cg.shared.global [%0], [%1], 16;"
                 :: "r"(dst), "l"((unsigned long long)__cvta_generic_to_global(src)));
}
__device__ __forceinline__ void cp16ca(uint32_t dst, const void* src) {
    asm volatile("cp.async.ca.shared.global [%0], [%1], 16;"
                 :: "r"(dst), "l"((unsigned long long)__cvta_generic_to_global(src)));
}
__device__ __forceinline__ void ldm4(uint32_t addr, uint32_t* r) {
    asm volatile("ldmatrix.sync.aligned.m8n8.x4.shared.b16 {%0,%1,%2,%3}, [%4];"
                 : "=r"(r[0]), "=r"(r[1]), "=r"(r[2]), "=r"(r[3]) : "r"(addr));
}
__device__ __forceinline__ void mma16816(float* c, const uint32_t* a,
                                         uint32_t b0, uint32_t b1) {
    asm volatile(
        "mma.sync.aligned.m16n8k16.row.col.f32.f16.f16.f32 "
        "{%0,%1,%2,%3}, {%4,%5,%6,%7}, {%8,%9}, {%0,%1,%2,%3};"
        : "+f"(c[0]), "+f"(c[1]), "+f"(c[2]), "+f"(c[3])
        : "r"(a[0]), "r"(a[1]), "r"(a[2]), "r"(a[3]), "r"(b0), "r"(b1));
}

// ---------------- per-batch mean / rstd over (P1, L) fp32 input ----------------
// Also zeroes the per-batch y accumulators.
__global__ void batch_stats(const float* __restrict__ x,
                            float* __restrict__ mu, float* __restrict__ rstd,
                            float* __restrict__ ysum, float* __restrict__ ysumsq) {
    const int NPER = P1c * Lc;
    const int b = blockIdx.x;
    const float4* xb = reinterpret_cast<const float4*>(x) + (size_t)b * (NPER / 4);
    float s = 0.f, ss = 0.f;
    for (int i = threadIdx.x; i < NPER / 4; i += blockDim.x) {
        float4 v = xb[i];
        s  += (v.x + v.y) + (v.z + v.w);
        ss += v.x * v.x + v.y * v.y + v.z * v.z + v.w * v.w;
    }
    __shared__ float sh_s[32], sh_ss[32];
    const int lane = threadIdx.x & 31, wid = threadIdx.x >> 5;
    for (int o = 16; o > 0; o >>= 1) {
        s  += __shfl_xor_sync(0xFFFFFFFFu, s,  o);
        ss += __shfl_xor_sync(0xFFFFFFFFu, ss, o);
    }
    if (lane == 0) { sh_s[wid] = s; sh_ss[wid] = ss; }
    __syncthreads();
    if (wid == 0) {
        const int nw = blockDim.x >> 5;
        s  = (lane < nw) ? sh_s[lane]  : 0.f;
        ss = (lane < nw) ? sh_ss[lane] : 0.f;
        for (int o = 16; o > 0; o >>= 1) {
            s  += __shfl_xor_sync(0xFFFFFFFFu, s,  o);
            ss += __shfl_xor_sync(0xFFFFFFFFu, ss, o);
        }
        if (lane == 0) {
            float m = s / NPER;
            float var = ss / NPER - m * m;
            mu[b] = m;
            rstd[b] = rsqrtf(var + 1e-5f);
            ysum[b] = 0.f;
            ysumsq[b] = 0.f;
        }
    }
}

// ---------------- LN(fp32 in) -> fp16 ----------------
__global__ void ln_fp16(const float* __restrict__ x,
                        const float* __restrict__ mu, const float* __restrict__ rstd,
                        const float* __restrict__ g, const float* __restrict__ bb,
                        __half* __restrict__ out) {
    size_t idx = (size_t)blockIdx.x * blockDim.x + threadIdx.x;
    int row = (int)(idx >> 7);
    int c4  = (int)(idx & 127) << 2;
    int b = row >> 6, p = row & 63;
    float m = mu[b], r = rstd[b];
    float4 v  = *(const float4*)&x[(size_t)row * Lc + c4];
    float4 gv = *(const float4*)&g[p * Lc + c4];
    float4 bv = *(const float4*)&bb[p * Lc + c4];
    ushort4 h4;
    h4.x = __half_as_ushort(__float2half((v.x - m) * r * gv.x + bv.x));
    h4.y = __half_as_ushort(__float2half((v.y - m) * r * gv.y + bv.y));
    h4.z = __half_as_ushort(__float2half((v.z - m) * r * gv.z + bv.z));
    h4.w = __half_as_ushort(__float2half((v.w - m) * r * gv.w + bv.w));
    *(ushort4*)&out[(size_t)row * Lc + c4] = h4;
}

// ---------------- LN2 (fp16 in) with inline stats finalize -> fp16 ----------------
__global__ void ln_fp16_h(const __half* __restrict__ x,
                          const float* __restrict__ ysum, const float* __restrict__ ysumsq,
                          const float* __restrict__ g, const float* __restrict__ bb,
                          __half* __restrict__ out) {
    size_t idx = (size_t)blockIdx.x * blockDim.x + threadIdx.x;
    int row = (int)(idx >> 7);
    int c4  = (int)(idx & 127) << 2;
    int b = row >> 6, p = row & 63;
    const float inv = 1.f / (P1c * Lc);
    float m = ysum[b] * inv;
    float r = rsqrtf(ysumsq[b] * inv - m * m + 1e-5f);
    ushort4 xv = *(const ushort4*)&x[(size_t)row * Lc + c4];
    float4 gv = *(const float4*)&g[p * Lc + c4];
    float4 bv = *(const float4*)&bb[p * Lc + c4];
    ushort4 h4;
    h4.x = __half_as_ushort(__float2half((__half2float(__ushort_as_half(xv.x)) - m) * r * gv.x + bv.x));
    h4.y = __half_as_ushort(__float2half((__half2float(__ushort_as_half(xv.y)) - m) * r * gv.y + bv.y));
    h4.z = __half_as_ushort(__float2half((__half2float(__ushort_as_half(xv.z)) - m) * r * gv.z + bv.z));
    h4.w = __half_as_ushort(__float2half((__half2float(__ushort_as_half(xv.w)) - m) * r * gv.w + bv.w));
    *(ushort4*)&out[(size_t)row * Lc + c4] = h4;
}

// ---------------- combined weight prep: w1^T, w2^T, circulant C^T ----------------
// blocks [0,1024):   w1 [512,2048]  -> w1t [2048,512]
// blocks [1024,2048): w2 [2048,512] -> w2t [512,2048]
// blocks [2048,2304): ct[n][k] = w[(n-k)&511]/sqrt(L), 1024 elems per block
__global__ void prep_weights(const float* __restrict__ w,
                             const float* __restrict__ w1,
                             const float* __restrict__ w2,
                             __half* __restrict__ ct,
                             __half* __restrict__ w1t,
                             __half* __restrict__ w2t) {
    __shared__ float t[32][33];
    const int tx = threadIdx.x, ty = threadIdx.y;
    const int bid = blockIdx.x;
    if (bid < 1024) {
        const int K = Lc, N = Hc;
        const int n0 = (bid & 63) * 32, k0 = (bid >> 6) * 32;
        for (int i = ty; i < 32; i += 8)
            t[i][tx] = w1[(size_t)(k0 + i) * N + n0 + tx];
        __syncthreads();
        for (int i = ty; i < 32; i += 8)
            w1t[(size_t)(n0 + i) * K + k0 + tx] = __float2half(t[tx][i]);
    } else if (bid < 2048) {
        const int K = Hc, N = Lc;
        const int b2 = bid - 1024;
        const int n0 = (b2 & 15) * 32, k0 = (b2 >> 4) * 32;
        for (int i = ty; i < 32; i += 8)
            t[i][tx] = w2[(size_t)(k0 + i) * N + n0 + tx];
        __syncthreads();
        for (int i = ty; i < 32; i += 8)
            w2t[(size_t)(n0 + i) * K + k0 + tx] = __float2half(t[tx][i]);
    } else {
        const int b3 = bid - 2048;                 // 0..255
        const int tid = ty * 32 + tx;              // 0..255
        const int base = b3 * 1024 + tid * 4;      // 4 elems per thread
        const int n = base >> 9;
        const int k = base & 511;
        const float s = 0.04419417382415922f;     // 1/sqrt(512)
        ushort4 h4;
        h4.x = __half_as_ushort(__float2half(w[(n - k)     & 511] * s));
        h4.y = __half_as_ushort(__float2half(w[(n - k - 1) & 511] * s));
        h4.z = __half_as_ushort(__float2half(w[(n - k - 2) & 511] * s));
        h4.w = __half_as_ushort(__float2half(w[(n - k - 3) & 511] * s));
        *(ushort4*)&ct[n * Lc + k] = h4;
    }
}

// ---------------- HMMA fp16 GEMM (exact R11/R15 best config — DO NOT TOUCH) ----
// CTA tile 128x128, BK=64, 4 warps (2M x 2N), warp tile 64x64.
// 2-stage cp.async pipeline, 3 CTAs/SM, B-frag halves (reg cap 170),
// B loaded with .ca. One sync per 64-deep k-tile.
// EPI 0: Dout=acc
// EPI 1: Z = fp16(relu(acc+bias))
// EPI 2: Dout=acc+bias+res
// EPI 3: Z = fp16(acc), plus per-batch sum/sumsq atomics (ysum/ysumsq)
#define RSTRIDE 144                     // 128B data + 16B pad per k64-row
#define MTILE_B (128 * RSTRIDE)         // 18432 per matrix
#define STG     (2 * MTILE_B)           // A, B = 36864
#define DSMEM   (2 * STG)               // 73728

template <int EPI, int K, int N>
__global__ void __launch_bounds__(128, 3)
hmma_gemm(const __half* __restrict__ A, const __half* __restrict__ B,
          float* __restrict__ Dout, __half* __restrict__ Z,
          const float* __restrict__ bias, const float* __restrict__ res,
          float* __restrict__ ysum, float* __restrict__ ysumsq) {
    extern __shared__ char smem[];
    const uint32_t sb = smem_u32(smem);
    const int tid = threadIdx.x, wid = tid >> 5, lane = tid & 31;
    const int wy = wid & 1, wx = wid >> 1;            // 2 M-warps x 2 N-warps
    const int m0 = blockIdx.y * 128, n0 = blockIdx.x * 128;

    const uint32_t offA = (uint32_t)((wy * 64 + (lane & 7) + ((lane >> 3) & 1) * 8) * RSTRIDE
                                     + (lane >> 4) * 16);
    const uint32_t offB = (uint32_t)((wx * 64 + (lane & 7) + (lane >> 4) * 8) * RSTRIDE
                                     + ((lane >> 3) & 1) * 16);

    auto load_stage = [&](int s, int kt) {
        const uint32_t ab = sb + s * STG;
#pragma unroll
        for (int i = 0; i < 8; i++) {
            const int j = tid + (i << 7);       // 0..1023
            const int row = j >> 3, c = j & 7;
            const uint32_t off = row * RSTRIDE + c * 16;
            cp16(ab + off, A + (size_t)(m0 + row) * K + (size_t)kt * 64 + c * 8);
            cp16ca(ab + MTILE_B + off,
                   B + (size_t)(n0 + row) * K + (size_t)kt * 64 + c * 8);
        }
        asm volatile("cp.async.commit_group;");
    };

    float acc[4][8][4];
#pragma unroll
    for (int mi = 0; mi < 4; mi++)
#pragma unroll
        for (int ni = 0; ni < 8; ni++)
#pragma unroll
            for (int q = 0; q < 4; q++) acc[mi][ni][q] = 0.f;

    constexpr int nkt = K >> 6;       // 8 / 8 / 32
    load_stage(0, 0);

    for (int kt = 0; kt < nkt; kt++) {
        asm volatile("cp.async.wait_group 0;" ::: "memory");
        __syncthreads();
        if (kt + 1 < nkt) load_stage((kt + 1) & 1, kt + 1);

        const uint32_t st = sb + (kt & 1) * STG;
#pragma unroll
        for (int kk = 0; kk < 4; kk++) {
            uint32_t ah[4][4];
#pragma unroll
            for (int mi = 0; mi < 4; mi++)
                ldm4(st + offA + mi * (16 * RSTRIDE) + kk * 32, ah[mi]);
#pragma unroll
            for (int half = 0; half < 2; half++) {
                uint32_t bf[2][4];
#pragma unroll
                for (int n2 = 0; n2 < 2; n2++)
                    ldm4(st + MTILE_B + offB + (half * 2 + n2) * (16 * RSTRIDE) + kk * 32,
                         bf[n2]);
#pragma unroll
                for (int mi = 0; mi < 4; mi++)
#pragma unroll
                    for (int n2 = 0; n2 < 2; n2++) {
                        const int nf = half * 2 + n2;
                        mma16816(acc[mi][nf * 2 + 0], ah[mi], bf[n2][0], bf[n2][1]);
                        mma16816(acc[mi][nf * 2 + 1], ah[mi], bf[n2][2], bf[n2][3]);
                    }
            }
        }
    }

    // ---- epilogue ----
    const int r0 = m0 + wy * 64 + (lane >> 2);
    const int cbase = n0 + wx * 64 + (lane & 3) * 2;
    float s = 0.f, ss = 0.f;
#pragma unroll
    for (int mi = 0; mi < 4; mi++) {
#pragma unroll
        for (int ni = 0; ni < 8; ni++) {
            const int col = cbase + ni * 8;
            const int ra = r0 + mi * 16;
            const int rb = ra + 8;
            float* c = acc[mi][ni];
            if (EPI == 0) {
                *(float2*)&Dout[(size_t)ra * N + col] = make_float2(c[0], c[1]);
                *(float2*)&Dout[(size_t)rb * N + col] = make_float2(c[2], c[3]);
            } else if (EPI == 1) {
                const float2 bq = *(const float2*)&bias[col];
                ushort2 h0, h1;
                h0.x = __half_as_ushort(__float2half(fmaxf(c[0] + bq.x, 0.f)));
                h0.y = __half_as_ushort(__float2half(fmaxf(c[1] + bq.y, 0.f)));
                h1.x = __half_as_ushort(__float2half(fmaxf(c[2] + bq.x, 0.f)));
                h1.y = __half_as_ushort(__float2half(fmaxf(c[3] + bq.y, 0.f)));
                *(ushort2*)&Z[(size_t)ra * N + col] = h0;
                *(ushort2*)&Z[(size_t)rb * N + col] = h1;
            } else if (EPI == 2) {
                const float2 bq = *(const float2*)&bias[col];
                const float2 q0 = *(const float2*)&res[(size_t)ra * N + col];
                const float2 q1 = *(const float2*)&res[(size_t)rb * N + col];
                *(float2*)&Dout[(size_t)ra * N + col] =
                    make_float2(c[0] + bq.x + q0.x, c[1] + bq.y + q0.y);
                *(float2*)&Dout[(size_t)rb * N + col] =
                    make_float2(c[2] + bq.x + q1.x, c[3] + bq.y + q1.y);
            } else {
                ushort2 h0, h1;
                h0.x = __half_as_ushort(__float2half(c[0]));
                h0.y = __half_as_ushort(__float2half(c[1]));
                h1.x = __half_as_ushort(__float2half(c[2]));
                h1.y = __half_as_ushort(__float2half(c[3]));
                *(ushort2*)&Z[(size_t)ra * N + col] = h0;
                *(ushort2*)&Z[(size_t)rb * N + col] = h1;
                s  += (c[0] + c[1]) + (c[2] + c[3]);
                ss += c[0] * c[0] + c[1] * c[1] + c[2] * c[2] + c[3] * c[3];
            }
        }
    }
    if (EPI == 3) {
        // warp rows m0 + wy*64 .. +63 lie in exactly one 64-row batch
#pragma unroll
        for (int o = 16; o > 0; o >>= 1) {
            s  += __shfl_xor_sync(0xFFFFFFFFu, s,  o);
            ss += __shfl_xor_sync(0xFFFFFFFFu, ss, o);
        }
        if (lane == 0) {
            const int b = (m0 >> 6) + wy;
            atomicAdd(&ysum[b],   s);
            atomicAdd(&ysumsq[b], ss);
        }
    }
}

// ---------------- launcher ----------------
extern "C" void kernel_launch(void* const* d_in, const int* in_sizes, int n_in,
                              void* d_out, int out_size) {
    const float* x    = (const float*)d_in[0];
    const float* w    = (const float*)d_in[1];
    const float* ln1w = (const float*)d_in[2];
    const float* ln1b = (const float*)d_in[3];
    const float* ln2w = (const float*)d_in[4];
    const float* ln2b = (const float*)d_in[5];
    const float* w1   = (const float*)d_in[6];
    const float* b1   = (const float*)d_in[7];
    const float* w2   = (const float*)d_in[8];
    const float* b2   = (const float*)d_in[9];
    float* out = (float*)d_out;

    float *mu1, *rstd1, *ysum, *ysumsq;
    __half *yh, *a1, *a2, *ct, *w1t, *w2t, *z;
    cudaGetSymbolAddress((void**)&mu1,    g_mu1);
    cudaGetSymbolAddress((void**)&rstd1,  g_rstd1);
    cudaGetSymbolAddress((void**)&ysum,   g_ysum);
    cudaGetSymbolAddress((void**)&ysumsq, g_ysumsq);
    cudaGetSymbolAddress((void**)&yh,     g_yh);
    cudaGetSymbolAddress((void**)&a1,     g_a1);
    cudaGetSymbolAddress((void**)&a2,     g_a2);
    cudaGetSymbolAddress((void**)&ct,     g_ct);
    cudaGetSymbolAddress((void**)&w1t,    g_w1t);
    cudaGetSymbolAddress((void**)&w2t,    g_w2t);
    cudaGetSymbolAddress((void**)&z,      g_z);

    cudaFuncSetAttribute(hmma_gemm<3, Lc, Lc>, cudaFuncAttributeMaxDynamicSharedMemorySize, DSMEM);
    cudaFuncSetAttribute(hmma_gemm<1, Lc, Hc>, cudaFuncAttributeMaxDynamicSharedMemorySize, DSMEM);
    cudaFuncSetAttribute(hmma_gemm<2, Hc, Lc>, cudaFuncAttributeMaxDynamicSharedMemorySize, DSMEM);

    // 1) LN1 stats (also zeroes y accumulators) + LN1 -> fp16
    batch_stats<<<Bb, 256>>>(x, mu1, rstd1, ysum, ysumsq);
    ln_fp16<<<(Mc * Lc / 4) / 256, 256>>>(x, mu1, rstd1, ln1w, ln1b, a1);
    // 2) combined operand prep (w1^T, w2^T, circulant C^T) in ONE launch
    prep_weights<<<2304, dim3(32, 8)>>>(w, w1, w2, ct, w1t, w2t);
    // 3) y = LN1(x) @ C  (fp16 out + fused stats)   M=32768 K=512 N=512
    hmma_gemm<3, Lc, Lc><<<dim3(Lc / 128, Mc / 128), 128, DSMEM>>>(
        a1, ct, nullptr, yh, nullptr, nullptr, ysum, ysumsq);
    // 4) LN2 -> fp16 (stats finalized inline from ysum/ysumsq)
    ln_fp16_h<<<(Mc * Lc / 4) / 256, 256>>>(yh, ysum, ysumsq, ln2w, ln2b, a2);
    // 5) z = fp16(relu(LN2(y) @ w1 + b1))   M=32768 K=512 N=2048
    hmma_gemm<1, Lc, Hc><<<dim3(Hc / 128, Mc / 128), 128, DSMEM>>>(
        a2, w1t, nullptr, z, b1, nullptr, nullptr, nullptr);
    // 6) out = z @ w2 + b2 + x              M=32768 K=2048 N=512
    hmma_gemm<2, Hc, Lc><<<dim3(Lc / 128, Mc / 128), 128, DSMEM>>>(
        z, w2t, out, nullptr, b2, x, nullptr, nullptr);
}